// round 15
// baseline (speedup 1.0000x reference)
#include <cuda_runtime.h>
#include <cstdint>
#include <cfloat>

#define NS 16384
#define NQ 16384
#define DIM 64
#define NC 64
#define QT 64
#define ST 64
#define NCHUNK (NS / ST)          // 256
#define ROWF 68                   // 64 data floats + 4 pad (272 B rows)
#define DELTA 2e-3f

// ---------------- device scratch ----------------
__device__ __align__(16) float g_sq_s[NS];
__device__ int g_lab[NS];
__device__ int g_flag_count;
__device__ int g_flag_q[NQ];

// ---------------- helpers ----------------
__device__ __forceinline__ uint32_t smem_u32(const void* p) {
    uint32_t a;
    asm("{ .reg .u64 t; cvta.to.shared.u64 t, %1; cvt.u32.u64 %0, t; }" : "=r"(a) : "l"(p));
    return a;
}
__device__ __forceinline__ unsigned long long fma2(unsigned long long a,
                                                   unsigned long long b,
                                                   unsigned long long c) {
    unsigned long long d;
    asm("fma.rn.f32x2 %0, %1, %2, %3;" : "=l"(d) : "l"(a), "l"(b), "l"(c));
    return d;
}
#define CP_ASYNC16(dst, src) \
    asm volatile("cp.async.cg.shared.global [%0], [%1], 16;" :: "r"(dst), "l"(src))
#define CP_COMMIT() asm volatile("cp.async.commit_group;" ::: "memory")
#define CP_WAIT1()  asm volatile("cp.async.wait_group 1;" ::: "memory")

// ---------------- prep: ||s||^2 + labels (4 threads per support row) ------
__global__ __launch_bounds__(256) void prep_kernel(const float* __restrict__ S,
                                                   const float* __restrict__ OH) {
    int gid = blockIdx.x * blockDim.x + threadIdx.x;   // 65536 threads
    if (gid == 0) g_flag_count = 0;
    int row = gid >> 2;
    int seg = gid & 3;
    int kb  = seg * 16;

    float ps = 0.f;
    #pragma unroll
    for (int i = 0; i < 4; i++) {
        float4 sv = *(const float4*)(S + (size_t)row * DIM + kb + i * 4);
        ps += sv.x * sv.x + sv.y * sv.y + sv.z * sv.z + sv.w * sv.w;
    }
    #pragma unroll
    for (int off = 1; off <= 2; off <<= 1)
        ps += __shfl_xor_sync(0xffffffffu, ps, off);

    float best = -1.f;
    int bi = kb;
    const float4* oh = (const float4*)(OH + (size_t)row * NC + kb);
    #pragma unroll
    for (int i = 0; i < 4; i++) {
        float4 v = oh[i];
        float vv[4] = {v.x, v.y, v.z, v.w};
        #pragma unroll
        for (int j = 0; j < 4; j++)
            if (vv[j] > best) { best = vv[j]; bi = kb + i * 4 + j; }
    }
    #pragma unroll
    for (int off = 1; off <= 2; off <<= 1) {
        float ob = __shfl_xor_sync(0xffffffffu, best, off);
        int   oi = __shfl_xor_sync(0xffffffffu, bi, off);
        if (ob > best || (ob == best && oi < bi)) { best = ob; bi = oi; }
    }
    if (seg == 0) { g_sq_s[row] = ps; g_lab[row] = bi; }
}

// ---------------- main FFMA2 kernel (natural layout, K-split) -------------
// smem: Q 64*272=17408 | S 2*64*272=34816 | sqs 2*256 | lab 256
#define OFF_Q   0
#define OFF_S   17408
#define OFF_SQ  52224
#define OFF_LAB 52736
#define SMEM_SZ 52992

__device__ __forceinline__ void issueS(uint32_t sbase, const float* __restrict__ S,
                                       int t, int buf, int tid) {
    const char* src = (const char*)(S + (size_t)t * ST * DIM);
    uint32_t dst = sbase + OFF_S + (uint32_t)buf * (ST * ROWF * 4);
    #pragma unroll
    for (int j = 0; j < 4; j++) {
        int e = tid + j * 256;          // 1024 x 16B chunks
        int row = e >> 4;
        int c = e & 15;
        CP_ASYNC16(dst + (uint32_t)row * (ROWF * 4) + (uint32_t)c * 16,
                   src + (size_t)e * 16);
    }
    if (tid < 16) {
        const char* sq = (const char*)(g_sq_s + t * ST);
        CP_ASYNC16(sbase + OFF_SQ + (uint32_t)buf * 256 + (uint32_t)tid * 16,
                   sq + tid * 16);
    }
}

__global__ __launch_bounds__(256, 2) void knn_kernel(const float* __restrict__ S,
                                                     const float* __restrict__ Q,
                                                     float* __restrict__ out) {
    extern __shared__ __align__(16) char smem[];
    const uint32_t sbase = smem_u32(smem);
    const int tid  = threadIdx.x;
    const int lane = tid & 31;
    const int w    = tid >> 5;
    const int tx   = lane & 7;          // support lane: s = tx + 8j
    const int qsub = lane >> 3;         // 0..3
    const int qg   = w * 4 + qsub;      // query group: queries {2qg, 2qg+1}
    const int qbase = blockIdx.x * QT;

    float* qsm = (float*)(smem + OFF_Q);
    float* ssm = (float*)(smem + OFF_S);
    float* sqs = (float*)(smem + OFF_SQ);
    int*   lab = (int*)(smem + OFF_LAB);

    // ---- Q tile: 64 rows x 64 floats into padded rows ----
    #pragma unroll
    for (int j = 0; j < 4; j++) {
        int e = tid + j * 256;
        int r = e >> 4;
        int c = e & 15;
        *(float4*)(qsm + r * ROWF + c * 4) =
            *(const float4*)(Q + (size_t)(qbase + r) * DIM + c * 4);
    }
    // ---- prologue: chunks 0,1 via cp.async ----
    issueS(sbase, S, 0, 0, tid);
    CP_COMMIT();
    issueS(sbase, S, 1, 1, tid);
    CP_COMMIT();
    __syncthreads();

    const float* q0 = qsm + (qg * 2) * ROWF;
    const float* q1 = q0 + ROWF;

    float m1[2], m2[2];
    int   i1[2];
    #pragma unroll
    for (int i = 0; i < 2; i++) { m1[i] = FLT_MAX; m2[i] = FLT_MAX; i1[i] = 0; }

    for (int t = 0; t < NCHUNK; t++) {
        const int buf = t & 1;
        CP_WAIT1();
        __syncthreads();

        const float* sb = ssm + buf * (ST * ROWF);

        unsigned long long acc[2][8];
        #pragma unroll
        for (int i = 0; i < 2; i++)
            #pragma unroll
            for (int j = 0; j < 8; j++) acc[i][j] = 0ull;

        #pragma unroll
        for (int k0 = 0; k0 < DIM; k0 += 4) {
            ulonglong2 qa = *(const ulonglong2*)(q0 + k0);
            ulonglong2 qb = *(const ulonglong2*)(q1 + k0);
            ulonglong2 sv[8];
            #pragma unroll
            for (int j = 0; j < 8; j++)
                sv[j] = *(const ulonglong2*)(sb + (tx + 8 * j) * ROWF + k0);
            #pragma unroll
            for (int j = 0; j < 8; j++) {
                acc[0][j] = fma2(qa.x, sv[j].x, acc[0][j]);
                acc[0][j] = fma2(qa.y, sv[j].y, acc[0][j]);
                acc[1][j] = fma2(qb.x, sv[j].x, acc[1][j]);
                acc[1][j] = fma2(qb.y, sv[j].y, acc[1][j]);
            }
        }

        // epilogue: cross = even+odd partial; d2' = ||s||^2 - 2*cross; top-2
        const float* sq = sqs + buf * 64;
        #pragma unroll
        for (int j = 0; j < 8; j++) {
            const int idx = t * ST + tx + 8 * j;
            float sqv = sq[tx + 8 * j];
            #pragma unroll
            for (int i = 0; i < 2; i++) {
                float lo = __uint_as_float((unsigned)(acc[i][j] & 0xffffffffull));
                float hi = __uint_as_float((unsigned)(acc[i][j] >> 32));
                float d = fmaf(-2.f, lo + hi, sqv);
                if (d < m1[i])      { m2[i] = m1[i]; m1[i] = d; i1[i] = idx; }
                else if (d < m2[i]) { m2[i] = d; }
            }
        }

        __syncthreads();
        if (t + 2 < NCHUNK) issueS(sbase, S, t + 2, buf, tid);
        CP_COMMIT();
    }

    // ---- reduce over tx (8 lanes per query), lexicographic, top-2 ----
    #pragma unroll
    for (int i = 0; i < 2; i++) {
        float d = m1[i], e = m2[i];
        int   x = i1[i];
        #pragma unroll
        for (int off = 4; off > 0; off >>= 1) {
            float od = __shfl_down_sync(0xffffffffu, d, off, 8);
            float oe = __shfl_down_sync(0xffffffffu, e, off, 8);
            int   ox = __shfl_down_sync(0xffffffffu, x, off, 8);
            if (od < d || (od == d && ox < x)) { e = fminf(d, oe); d = od; x = ox; }
            else                               { e = fminf(e, od); }
        }
        if (tx == 0) {
            int qi = qg * 2 + i;
            if (e - d < DELTA) {
                int slot = atomicAdd(&g_flag_count, 1);
                g_flag_q[slot] = qbase + qi;
            }
            lab[qi] = g_lab[x];
        }
    }
    __syncthreads();

    // ---- one-hot write: 64 rows x 64 cols = 1024 float4 ----
    #pragma unroll
    for (int j = 0; j < 4; j++) {
        int e = tid + j * 256;
        int row = e >> 4;
        int c4 = (e & 15) * 4;
        int lb = lab[row];
        float4 v;
        v.x = (c4 + 0 == lb) ? 1.f : 0.f;
        v.y = (c4 + 1 == lb) ? 1.f : 0.f;
        v.z = (c4 + 2 == lb) ? 1.f : 0.f;
        v.w = (c4 + 3 == lb) ? 1.f : 0.f;
        *(float4*)(out + (size_t)(qbase + row) * NC + c4) = v;
    }
}

// ---------------- exact cleanup for flagged queries ----------------
__global__ __launch_bounds__(256) void cleanup_kernel(const float* __restrict__ S,
                                                      const float* __restrict__ Q,
                                                      float* __restrict__ out) {
    __shared__ float qrow[DIM];
    __shared__ float bd[256];
    __shared__ int   bix[256];
    const int tid = threadIdx.x;
    const int nflag = g_flag_count;
    for (int f = blockIdx.x; f < nflag; f += gridDim.x) {
        int q = g_flag_q[f];
        if (tid < DIM) qrow[tid] = Q[(size_t)q * DIM + tid];
        __syncthreads();
        float best = FLT_MAX;
        int bidx = 0;
        for (int s = tid; s < NS; s += 256) {
            const float* sr = S + (size_t)s * DIM;
            float acc = 0.f;
            #pragma unroll
            for (int k = 0; k < DIM; k++) acc = fmaf(qrow[k], sr[k], acc);
            float d2 = fmaf(-2.f, acc, g_sq_s[s]);   // same shifted metric
            if (d2 < best) { best = d2; bidx = s; }
        }
        bd[tid] = best; bix[tid] = bidx;
        __syncthreads();
        for (int off = 128; off > 0; off >>= 1) {
            if (tid < off) {
                float od = bd[tid + off]; int oi = bix[tid + off];
                if (od < bd[tid] || (od == bd[tid] && oi < bix[tid])) {
                    bd[tid] = od; bix[tid] = oi;
                }
            }
            __syncthreads();
        }
        int lb = g_lab[bix[0]];
        if (tid < NC) out[(size_t)q * NC + tid] = (tid == lb) ? 1.f : 0.f;
        __syncthreads();
    }
}

// ---------------- launch ----------------
extern "C" void kernel_launch(void* const* d_in, const int* in_sizes, int n_in,
                              void* d_out, int out_size) {
    const float* S  = (const float*)d_in[0];
    const float* Q  = (const float*)d_in[1];
    const float* OH = (const float*)d_in[2];
    float* out = (float*)d_out;

    static bool attr_set = false;
    if (!attr_set) {
        cudaFuncSetAttribute(knn_kernel,
                             cudaFuncAttributeMaxDynamicSharedMemorySize, SMEM_SZ);
        attr_set = true;
    }

    prep_kernel<<<NS / 64, 256>>>(S, OH);
    knn_kernel<<<NQ / QT, 256, SMEM_SZ>>>(S, Q, out);
    cleanup_kernel<<<128, 256>>>(S, Q, out);
}

// round 17
// speedup vs baseline: 2.0554x; 2.0554x over previous
#include <cuda_runtime.h>
#include <cstdint>
#include <cfloat>

#define NS 16384
#define NQ 16384
#define DIM 64
#define NC 64
#define QT 64
#define ST 128
#define NCHUNK (NS / ST)          // 128

// ---------------- device scratch ----------------
__device__ __align__(16) float g_sq_s[NS];
__device__ int g_lab[NS];
__device__ __align__(16) float g_St[DIM * NS];       // [k][s]   4 MB
__device__ __align__(16) float g_Qd[DIM * 2 * NQ];   // [k][2q]  8 MB (duplicated)

// ---------------- helpers ----------------
__device__ __forceinline__ uint32_t smem_u32(const void* p) {
    uint32_t a;
    asm("{ .reg .u64 t; cvta.to.shared.u64 t, %1; cvt.u32.u64 %0, t; }" : "=r"(a) : "l"(p));
    return a;
}
__device__ __forceinline__ unsigned long long fma2(unsigned long long a,
                                                   unsigned long long b,
                                                   unsigned long long c) {
    unsigned long long d;
    asm("fma.rn.f32x2 %0, %1, %2, %3;" : "=l"(d) : "l"(a), "l"(b), "l"(c));
    return d;
}
#define CP_ASYNC16(dst, src) \
    asm volatile("cp.async.cg.shared.global [%0], [%1], 16;" :: "r"(dst), "l"(src))
#define CP_COMMIT() asm volatile("cp.async.commit_group;" ::: "memory")
#define CP_WAIT1()  asm volatile("cp.async.wait_group 1;" ::: "memory")

// ---------------- prep 1: ||s||^2 + labels ----------------
__global__ __launch_bounds__(256) void prep_kernel(const float* __restrict__ S,
                                                   const float* __restrict__ OH) {
    int gid = blockIdx.x * blockDim.x + threadIdx.x;   // 65536 threads
    int row = gid >> 2;
    int seg = gid & 3;
    int kb  = seg * 16;

    float ps = 0.f;
    #pragma unroll
    for (int i = 0; i < 4; i++) {
        float4 sv = *(const float4*)(S + (size_t)row * DIM + kb + i * 4);
        ps += sv.x * sv.x + sv.y * sv.y + sv.z * sv.z + sv.w * sv.w;
    }
    #pragma unroll
    for (int off = 1; off <= 2; off <<= 1)
        ps += __shfl_xor_sync(0xffffffffu, ps, off);

    float best = -1.f;
    int bi = kb;
    const float4* oh = (const float4*)(OH + (size_t)row * NC + kb);
    #pragma unroll
    for (int i = 0; i < 4; i++) {
        float4 v = oh[i];
        float vv[4] = {v.x, v.y, v.z, v.w};
        #pragma unroll
        for (int j = 0; j < 4; j++)
            if (vv[j] > best) { best = vv[j]; bi = kb + i * 4 + j; }
    }
    #pragma unroll
    for (int off = 1; off <= 2; off <<= 1) {
        float ob = __shfl_xor_sync(0xffffffffu, best, off);
        int   oi = __shfl_xor_sync(0xffffffffu, bi, off);
        if (ob > best || (ob == best && oi < bi)) { best = ob; bi = oi; }
    }
    if (seg == 0) { g_sq_s[row] = ps; g_lab[row] = bi; }
}

// ---------------- prep 2: GMEM transpose (S -> [k][s], Q -> [k][2q] dup) ---
// grid (64, 16): blockIdx.x covers rows (256 each), blockIdx.y = k-slice of 4.
__global__ __launch_bounds__(256) void transpose_kernel(const float* __restrict__ S,
                                                        const float* __restrict__ Q) {
    int r  = blockIdx.x * 256 + threadIdx.x;    // 0..16383, coalesced per warp
    int k4 = blockIdx.y * 4;                    // k group of 4

    float4 sv = *(const float4*)(S + (size_t)r * DIM + k4);
    float4 qv = *(const float4*)(Q + (size_t)r * DIM + k4);
    float svv[4] = {sv.x, sv.y, sv.z, sv.w};
    float qvv[4] = {qv.x, qv.y, qv.z, qv.w};
    #pragma unroll
    for (int c = 0; c < 4; c++) {
        g_St[(size_t)(k4 + c) * NS + r] = svv[c];
        uint32_t b = __float_as_uint(qvv[c]);
        unsigned long long d = ((unsigned long long)b << 32) | b;
        *(unsigned long long*)(g_Qd + (size_t)(k4 + c) * (2 * NQ) + 2 * r) = d;
    }
}

// ---------------- main FFMA2 kernel ----------------
// smem: Qdup [64][128] 32KB | S 2x[64][128] 64KB | sqs 2x512B | idx 256B | lab 256B
#define OFF_Q   0
#define OFF_S   32768
#define OFF_SQ  98304
#define OFF_IDX 99328
#define OFF_LAB 99584
#define SMEM_SZ 99840

__device__ __forceinline__ void issueS(uint32_t sbase, int t, int buf, int tid) {
    const char* src = (const char*)g_St;       // row k stride = NS floats
    uint32_t dst = sbase + OFF_S + (uint32_t)buf * 32768;
    #pragma unroll
    for (int j = 0; j < 8; j++) {
        int e = tid + j * 256;                 // 2048 x 16B
        int k = e >> 5;
        int c = e & 31;
        CP_ASYNC16(dst + (uint32_t)k * 512 + (uint32_t)c * 16,
                   src + (size_t)k * (NS * 4) + (size_t)t * 512 + (size_t)c * 16);
    }
    if (tid < 32) {
        const char* sq = (const char*)(g_sq_s + t * ST);
        CP_ASYNC16(sbase + OFF_SQ + (uint32_t)buf * 512 + (uint32_t)tid * 16,
                   sq + tid * 16);
    }
}

__global__ __launch_bounds__(256, 2) void knn_kernel(float* __restrict__ out) {
    extern __shared__ __align__(16) char smem[];
    const uint32_t sbase = smem_u32(smem);
    const int tid  = threadIdx.x;
    const int lane = tid & 31;
    const int tx   = lane & 15;                 // support slot
    const int ty   = (tid >> 5) * 2 + (lane >> 4);   // query group 0..15
    const int qbase = blockIdx.x * QT;

    float* qsm = (float*)(smem + OFF_Q);
    float* ssm = (float*)(smem + OFF_S);
    float* sqs = (float*)(smem + OFF_SQ);
    int* idx_sh = (int*)(smem + OFF_IDX);
    int* lab    = (int*)(smem + OFF_LAB);

    // ---- Q tile: [64 k][128] from pre-duplicated g_Qd (coalesced) ----
    {
        const char* src = (const char*)g_Qd;
        char* dst = smem + OFF_Q;
        #pragma unroll
        for (int j = 0; j < 8; j++) {
            int e = tid + j * 256;              // 2048 x 16B
            int k = e >> 5;
            int c = e & 31;
            *(uint4*)(dst + (uint32_t)k * 512 + (uint32_t)c * 16) =
                *(const uint4*)(src + (size_t)k * (2 * NQ * 4) +
                                (size_t)qbase * 8 + (size_t)c * 16);
        }
    }
    // ---- prologue: S chunks 0,1 ----
    issueS(sbase, 0, 0, tid);
    CP_COMMIT();
    issueS(sbase, 1, 1, tid);
    CP_COMMIT();
    __syncthreads();

    const unsigned long long NEG2 = 0xC0000000C0000000ull;
    const float* qb = qsm + ty * 8;

    float m1[4];
    int   i1[4];
    #pragma unroll
    for (int i = 0; i < 4; i++) { m1[i] = FLT_MAX; i1[i] = 0; }

    for (int t = 0; t < NCHUNK; t++) {
        const int buf = t & 1;
        CP_WAIT1();
        __syncthreads();

        const float* sb = ssm + buf * 8192 + tx * 4;

        unsigned long long acc[4][4];
        #pragma unroll
        for (int i = 0; i < 4; i++)
            #pragma unroll
            for (int p = 0; p < 4; p++) acc[i][p] = 0ull;

        #pragma unroll 8
        for (int k = 0; k < DIM; k++) {
            const float* qp = qb + k * 128;
            ulonglong2 qa = *(const ulonglong2*)(qp);
            ulonglong2 qc = *(const ulonglong2*)(qp + 4);
            const float* sp = sb + k * 128;
            ulonglong2 sa = *(const ulonglong2*)(sp);
            ulonglong2 sc = *(const ulonglong2*)(sp + 64);
            unsigned long long qv[4] = {qa.x, qa.y, qc.x, qc.y};
            unsigned long long sv[4] = {sa.x, sa.y, sc.x, sc.y};
            #pragma unroll
            for (int i = 0; i < 4; i++)
                #pragma unroll
                for (int p = 0; p < 4; p++)
                    acc[i][p] = fma2(qv[i], sv[p], acc[i][p]);
        }

        // epilogue: d2' = ||s||^2 - 2*cross (||q||^2 dropped: argmin-invariant)
        const float* sq = sqs + buf * 128 + tx * 4;
        unsigned long long sqp[4] = {
            *(const unsigned long long*)(sq),
            *(const unsigned long long*)(sq + 2),
            *(const unsigned long long*)(sq + 64),
            *(const unsigned long long*)(sq + 66)};
        const int base = t * ST + tx * 4;
        #pragma unroll
        for (int p = 0; p < 4; p++) {
            const int idx0 = base + (p >> 1) * 64 + (p & 1) * 2;
            #pragma unroll
            for (int i = 0; i < 4; i++) {
                unsigned long long d2 = fma2(NEG2, acc[i][p], sqp[p]);
                float lo = __uint_as_float((unsigned)(d2 & 0xffffffffull));
                float hi = __uint_as_float((unsigned)(d2 >> 32));
                if (lo < m1[i]) { m1[i] = lo; i1[i] = idx0; }
                if (hi < m1[i]) { m1[i] = hi; i1[i] = idx0 + 1; }
            }
        }

        __syncthreads();
        if (t + 2 < NCHUNK) issueS(sbase, t + 2, buf, tid);
        CP_COMMIT();
    }

    // ---- reduce over tx (16 lanes per query), lexicographic ----
    #pragma unroll
    for (int i = 0; i < 4; i++) {
        float d = m1[i];
        int   x = i1[i];
        #pragma unroll
        for (int off = 8; off > 0; off >>= 1) {
            float od = __shfl_down_sync(0xffffffffu, d, off, 16);
            int   ox = __shfl_down_sync(0xffffffffu, x, off, 16);
            if (od < d || (od == d && ox < x)) { d = od; x = ox; }
        }
        if (tx == 0) idx_sh[ty * 4 + i] = x;
    }
    __syncthreads();

    if (tid < QT) lab[tid] = g_lab[idx_sh[tid]];
    __syncthreads();

    // ---- one-hot write: 64 rows x 64 cols ----
    #pragma unroll
    for (int j = 0; j < 4; j++) {
        int e = tid + j * 256;
        int row = e >> 4;
        int c4 = (e & 15) * 4;
        int lb = lab[row];
        float4 v;
        v.x = (c4 + 0 == lb) ? 1.f : 0.f;
        v.y = (c4 + 1 == lb) ? 1.f : 0.f;
        v.z = (c4 + 2 == lb) ? 1.f : 0.f;
        v.w = (c4 + 3 == lb) ? 1.f : 0.f;
        *(float4*)(out + (size_t)(qbase + row) * NC + c4) = v;
    }
}

// ---------------- launch ----------------
extern "C" void kernel_launch(void* const* d_in, const int* in_sizes, int n_in,
                              void* d_out, int out_size) {
    const float* S  = (const float*)d_in[0];
    const float* Q  = (const float*)d_in[1];
    const float* OH = (const float*)d_in[2];
    float* out = (float*)d_out;

    static bool attr_set = false;
    if (!attr_set) {
        cudaFuncSetAttribute(knn_kernel,
                             cudaFuncAttributeMaxDynamicSharedMemorySize, SMEM_SZ);
        attr_set = true;
    }

    prep_kernel<<<NS / 64, 256>>>(S, OH);
    transpose_kernel<<<dim3(NS / 256, DIM / 4), 256>>>(S, Q);
    knn_kernel<<<NQ / QT, 256, SMEM_SZ>>>(out);
}